// round 7
// baseline (speedup 1.0000x reference)
#include <cuda_runtime.h>

#define NNODES 100000
#define NEDGES 3200000
#define DIN 64
#define HID 16
#define SCAN_BLK 1024
#define SCAN_CHUNK 4096
#define NSCANBLK 25   // ceil(NNODES / SCAN_CHUNK)

// ---------------- device scratch (no allocations allowed) -------------------
__device__ __align__(256) float g_p1[NNODES * HID];     // x@W1x + b_msg1
__device__ __align__(256) float g_s1[NNODES * HID];     // x@W_skip1 + b_skip1
__device__ __align__(256) float g_p2[NNODES * HID];     // h@W2x + b_msg2
__device__ __align__(256) float g_s2[NNODES * HID];     // h@W_skip2 + b_skip2
__device__ __align__(256) float g_acce[NNODES * HID];   // per-node sum of edge_attr (scatter)
__device__ __align__(256) unsigned g_deg[NNODES];
__device__ __align__(256) unsigned g_off[NNODES + 1];
__device__ __align__(256) unsigned g_cur[NNODES];
__device__ __align__(256) unsigned g_srcs[NEDGES];      // src ids sorted by dst (CSR)
__device__ unsigned g_bsum[NSCANBLK];
__device__ unsigned g_boff[NSCANBLK];

__device__ __forceinline__ void red_v4(float* addr, float4 v) {
    asm volatile("red.global.add.v4.f32 [%0], {%1,%2,%3,%4};"
                 :: "l"(addr), "f"(v.x), "f"(v.y), "f"(v.z), "f"(v.w)
                 : "memory");
}

// ---------------------------------------------------------------------------
// K0: zero acc_e (6.4 MB) + degree counters
// ---------------------------------------------------------------------------
__global__ __launch_bounds__(256) void k_zero() {
    int i = blockIdx.x * blockDim.x + threadIdx.x;
    const int nacc = NNODES * 4;                       // g_acce as float4
    if (i < nacc) reinterpret_cast<float4*>(g_acce)[i] = make_float4(0.f, 0.f, 0.f, 0.f);
    else if (i < nacc + NNODES) g_deg[i - nacc] = 0u;
}

// ---------------------------------------------------------------------------
// K1: histogram of dst
// ---------------------------------------------------------------------------
__global__ __launch_bounds__(256) void k_hist(const int* __restrict__ dst) {
    int i = blockIdx.x * blockDim.x + threadIdx.x;
    if (i < NEDGES / 4) {
        int4 d = __ldg(reinterpret_cast<const int4*>(dst) + i);
        atomicAdd(&g_deg[d.x], 1u);
        atomicAdd(&g_deg[d.y], 1u);
        atomicAdd(&g_deg[d.z], 1u);
        atomicAdd(&g_deg[d.w], 1u);
    }
}

// ---------------------------------------------------------------------------
// K2a/b/c: exclusive prefix scan of g_deg -> g_off (two-level)
// ---------------------------------------------------------------------------
__global__ __launch_bounds__(SCAN_BLK) void k_scan1() {
    __shared__ unsigned swarp[32];
    int t = threadIdx.x;
    int base = blockIdx.x * SCAN_CHUNK + t * 4;
    unsigned v[4];
    #pragma unroll
    for (int i = 0; i < 4; i++) v[i] = (base + i < NNODES) ? g_deg[base + i] : 0u;
    unsigned s = v[0] + v[1] + v[2] + v[3];
    unsigned lane = t & 31, wid = t >> 5;
    unsigned inc = s;
    #pragma unroll
    for (int o = 1; o < 32; o <<= 1) {
        unsigned n = __shfl_up_sync(~0u, inc, o);
        if (lane >= o) inc += n;
    }
    if (lane == 31) swarp[wid] = inc;
    __syncthreads();
    if (wid == 0) {
        unsigned wv = swarp[lane];
        #pragma unroll
        for (int o = 1; o < 32; o <<= 1) {
            unsigned n = __shfl_up_sync(~0u, wv, o);
            if (lane >= o) wv += n;
        }
        swarp[lane] = wv;
    }
    __syncthreads();
    unsigned run = inc - s + (wid ? swarp[wid - 1] : 0u);
    #pragma unroll
    for (int i = 0; i < 4; i++) {
        if (base + i < NNODES) g_off[base + i] = run;
        run += v[i];
    }
    if (t == 0) g_bsum[blockIdx.x] = swarp[31];
}

__global__ void k_scan2() {
    int lane = threadIdx.x;
    unsigned v = (lane < NSCANBLK) ? g_bsum[lane] : 0u;
    unsigned inc = v;
    #pragma unroll
    for (int o = 1; o < 32; o <<= 1) {
        unsigned n = __shfl_up_sync(~0u, inc, o);
        if (lane >= o) inc += n;
    }
    if (lane < NSCANBLK) g_boff[lane] = inc - v;
}

__global__ __launch_bounds__(256) void k_scan3() {
    int i = blockIdx.x * blockDim.x + threadIdx.x;
    if (i < NNODES) {
        unsigned val = g_off[i] + g_boff[i >> 12];   // /SCAN_CHUNK
        g_off[i] = val;
        g_cur[i] = val;
    }
    if (i == 0) g_off[NNODES] = NEDGES;
}

// ---------------------------------------------------------------------------
// K3: scatter src into dst-sorted CSR slots (4B payload)
// ---------------------------------------------------------------------------
__global__ __launch_bounds__(256) void k_scatter(const int* __restrict__ src,
                                                 const int* __restrict__ dst) {
    int e = blockIdx.x * blockDim.x + threadIdx.x;
    if (e < NEDGES) {
        int d = __ldg(dst + e);
        unsigned pos = atomicAdd(&g_cur[d], 1u);
        g_srcs[pos] = (unsigned)__ldg(src + e);
    }
}

// ---------------------------------------------------------------------------
// K4: streaming ea scatter — acc_e[dst] += edge_attr[e]  (4 lanes/edge, coalesced)
// ---------------------------------------------------------------------------
__global__ __launch_bounds__(256) void k_edge_ea(const int* __restrict__ dst,
                                                 const float* __restrict__ ea) {
    int tid = blockIdx.x * blockDim.x + threadIdx.x;
    if (tid >= NEDGES * 4) return;
    int i = tid >> 2, c = tid & 3;
    float4 e = reinterpret_cast<const float4*>(ea)[tid];   // coalesced stream
    int d = __ldg(dst + i);
    red_v4(g_acce + (size_t)d * HID + c * 4, e);
}

// ---------------------------------------------------------------------------
// K5: per-node p1 = x@W1x + b_msg1 ; s1 = x@W_skip1 + b_skip1
// ---------------------------------------------------------------------------
__global__ __launch_bounds__(256) void k_node1(
    const float* __restrict__ x,
    const float* __restrict__ Wm1, const float* __restrict__ bm1,
    const float* __restrict__ Ws1, const float* __restrict__ bs1)
{
    __shared__ float sWx[DIN * HID];
    __shared__ float sWs[DIN * HID];
    __shared__ float sx[16][DIN];
    int t = threadIdx.x;
    for (int i = t; i < DIN * HID; i += 256) { sWx[i] = Wm1[i]; sWs[i] = Ws1[i]; }
    int ln = t >> 4, j = t & 15;
    int v = blockIdx.x * 16 + ln;
    if (v < NNODES) {
        reinterpret_cast<float4*>(sx[ln])[j] =
            reinterpret_cast<const float4*>(x + (size_t)v * DIN)[j];
    }
    __syncthreads();
    if (v >= NNODES) return;
    float ap = bm1[j], as = bs1[j];
    #pragma unroll
    for (int k = 0; k < DIN; k++) {
        float xv = sx[ln][k];
        ap = fmaf(xv, sWx[k * HID + j], ap);
        as = fmaf(xv, sWs[k * HID + j], as);
    }
    g_p1[(size_t)v * HID + j] = ap;
    g_s1[(size_t)v * HID + j] = as;
}

// ---------------------------------------------------------------------------
// Batched gather: 4 segments of 8 edges in flight per lane (MLP=4 on both
// the index load and the dependent row load).
// ---------------------------------------------------------------------------
__device__ __forceinline__ float4 gather_sum(const float* __restrict__ tbl,
                                             unsigned beg, unsigned end,
                                             int slot, int c)
{
    float4 a0 = make_float4(0.f, 0.f, 0.f, 0.f);
    float4 a1 = a0, a2 = a0, a3 = a0;
    unsigned idx = beg + slot;
    for (; idx + 24 < end; idx += 32) {
        unsigned s0 = __ldg(g_srcs + idx);
        unsigned s1 = __ldg(g_srcs + idx + 8);
        unsigned s2 = __ldg(g_srcs + idx + 16);
        unsigned s3 = __ldg(g_srcs + idx + 24);
        float4 q0 = __ldg(reinterpret_cast<const float4*>(tbl + (size_t)s0 * HID) + c);
        float4 q1 = __ldg(reinterpret_cast<const float4*>(tbl + (size_t)s1 * HID) + c);
        float4 q2 = __ldg(reinterpret_cast<const float4*>(tbl + (size_t)s2 * HID) + c);
        float4 q3 = __ldg(reinterpret_cast<const float4*>(tbl + (size_t)s3 * HID) + c);
        a0.x += q0.x; a0.y += q0.y; a0.z += q0.z; a0.w += q0.w;
        a1.x += q1.x; a1.y += q1.y; a1.z += q1.z; a1.w += q1.w;
        a2.x += q2.x; a2.y += q2.y; a2.z += q2.z; a2.w += q2.w;
        a3.x += q3.x; a3.y += q3.y; a3.z += q3.z; a3.w += q3.w;
    }
    for (; idx < end; idx += 8) {
        unsigned s = __ldg(g_srcs + idx);
        float4 q = __ldg(reinterpret_cast<const float4*>(tbl + (size_t)s * HID) + c);
        a0.x += q.x; a0.y += q.y; a0.z += q.z; a0.w += q.w;
    }
    a0.x += a1.x + a2.x + a3.x;
    a0.y += a1.y + a2.y + a3.y;
    a0.z += a1.z + a2.z + a3.z;
    a0.w += a1.w + a2.w + a3.w;
    return a0;
}

// ---------------------------------------------------------------------------
// K6: conv1 gather-aggregate (p1 only, L2-resident) + fused node math
// ---------------------------------------------------------------------------
__global__ __launch_bounds__(256) void k_agg1(
    const float* __restrict__ Wm1,
    const float* __restrict__ Wm2, const float* __restrict__ bm2,
    const float* __restrict__ Ws2, const float* __restrict__ bs2)
{
    __shared__ float sWe1[HID * HID], sW2x[HID * HID], sWs2[HID * HID];
    __shared__ float sb2[HID], sbs2[HID];
    __shared__ float sacc[8][HID];
    __shared__ float sae[8][HID];
    __shared__ float sh[8][HID];
    int t = threadIdx.x;
    if (t < 256) { sWe1[t] = Wm1[DIN * HID + t]; sW2x[t] = Wm2[t]; sWs2[t] = Ws2[t]; }
    if (t < HID) { sb2[t] = bm2[t]; sbs2[t] = bs2[t]; }

    int w = t >> 5, lane = t & 31;
    int v = blockIdx.x * 8 + w;            // grid = NNODES/8 exactly
    int slot = lane >> 2, c = lane & 3;
    unsigned beg = g_off[v], end = g_off[v + 1];
    if (lane < HID) sae[w][lane] = g_acce[(size_t)v * HID + lane];

    float4 ap = gather_sum(g_p1, beg, end, slot, c);
    #pragma unroll
    for (int m = 4; m <= 16; m <<= 1) {
        ap.x += __shfl_xor_sync(~0u, ap.x, m);
        ap.y += __shfl_xor_sync(~0u, ap.y, m);
        ap.z += __shfl_xor_sync(~0u, ap.z, m);
        ap.w += __shfl_xor_sync(~0u, ap.w, m);
    }
    if (lane < 4) reinterpret_cast<float4*>(sacc[w])[lane] = ap;
    __syncthreads();

    int ln = t >> 4, j = t & 15;
    if (t < 128) {
        int v2 = blockIdx.x * 8 + ln;
        float hv = sacc[ln][j] + g_s1[(size_t)v2 * HID + j];
        #pragma unroll
        for (int k = 0; k < HID; k++) hv = fmaf(sae[ln][k], sWe1[k * HID + j], hv);
        sh[ln][j] = fmaxf(hv, 0.f);
    }
    __syncthreads();
    if (t < 128) {
        int v2 = blockIdx.x * 8 + ln;
        float pv = sb2[j], sv = sbs2[j];
        #pragma unroll
        for (int k = 0; k < HID; k++) {
            float hk = sh[ln][k];
            pv = fmaf(hk, sW2x[k * HID + j], pv);
            sv = fmaf(hk, sWs2[k * HID + j], sv);
        }
        g_p2[(size_t)v2 * HID + j] = pv;
        g_s2[(size_t)v2 * HID + j] = sv;
    }
}

// ---------------------------------------------------------------------------
// K7: conv2 gather-aggregate + fused final projection
// ---------------------------------------------------------------------------
__global__ __launch_bounds__(256) void k_agg2(
    const float* __restrict__ Wm2,
    const float* __restrict__ Wl3, const float* __restrict__ bl3,
    float* __restrict__ out)
{
    __shared__ float sWe2[HID * HID];
    __shared__ float sWl[HID * DIN];
    __shared__ float sbl[DIN];
    __shared__ float sacc[8][HID];
    __shared__ float sae[8][HID];
    __shared__ float sh2[8][HID];
    int t = threadIdx.x;
    if (t < 256) sWe2[t] = Wm2[HID * HID + t];
    for (int i = t; i < HID * DIN; i += 256) sWl[i] = Wl3[i];
    if (t < DIN) sbl[t] = bl3[t];

    int w = t >> 5, lane = t & 31;
    int v = blockIdx.x * 8 + w;
    int slot = lane >> 2, c = lane & 3;
    unsigned beg = g_off[v], end = g_off[v + 1];
    if (lane < HID) sae[w][lane] = g_acce[(size_t)v * HID + lane];

    float4 ap = gather_sum(g_p2, beg, end, slot, c);
    #pragma unroll
    for (int m = 4; m <= 16; m <<= 1) {
        ap.x += __shfl_xor_sync(~0u, ap.x, m);
        ap.y += __shfl_xor_sync(~0u, ap.y, m);
        ap.z += __shfl_xor_sync(~0u, ap.z, m);
        ap.w += __shfl_xor_sync(~0u, ap.w, m);
    }
    if (lane < 4) reinterpret_cast<float4*>(sacc[w])[lane] = ap;
    __syncthreads();

    int ln = t >> 4, j = t & 15;
    if (t < 128) {
        int v2 = blockIdx.x * 8 + ln;
        float hv = sacc[ln][j] + g_s2[(size_t)v2 * HID + j];
        #pragma unroll
        for (int k = 0; k < HID; k++) hv = fmaf(sae[ln][k], sWe2[k * HID + j], hv);
        sh2[ln][j] = hv;
    }
    __syncthreads();

    // 8 nodes x 64 outputs = 512 per block, 2 per thread
    #pragma unroll
    for (int r = 0; r < 2; r++) {
        int o = t + r * 256;
        int ln2 = o >> 6, col = o & 63;
        int v3 = blockIdx.x * 8 + ln2;
        float acc = sbl[col];
        #pragma unroll
        for (int k = 0; k < HID; k++) acc = fmaf(sh2[ln2][k], sWl[k * DIN + col], acc);
        out[(size_t)v3 * DIN + col] = acc;
    }
}

// ---------------------------------------------------------------------------
extern "C" void kernel_launch(void* const* d_in, const int* in_sizes, int n_in,
                              void* d_out, int out_size)
{
    const float* x   = (const float*)d_in[0];
    const int*   ei  = (const int*)  d_in[1];
    const float* ea  = (const float*)d_in[2];
    const float* Wm1 = (const float*)d_in[3];
    const float* bm1 = (const float*)d_in[4];
    const float* Ws1 = (const float*)d_in[5];
    const float* bs1 = (const float*)d_in[6];
    const float* Wm2 = (const float*)d_in[7];
    const float* bm2 = (const float*)d_in[8];
    const float* Ws2 = (const float*)d_in[9];
    const float* bs2 = (const float*)d_in[10];
    const float* Wl3 = (const float*)d_in[11];
    const float* bl3 = (const float*)d_in[12];
    const int* src = ei;
    const int* dst = ei + NEDGES;
    float* out = (float*)d_out;

    // Same launch order as R4 (profiled 4th launch = k_edge_ea, known 51us).
    k_zero   <<<(NNODES * 5 + 255) / 256, 256>>>();
    k_hist   <<<(NEDGES / 4 + 255) / 256, 256>>>(dst);
    k_scan1  <<<NSCANBLK, SCAN_BLK>>>();
    k_edge_ea<<<(NEDGES * 4 + 255) / 256, 256>>>(dst, ea);
    k_scan2  <<<1, 32>>>();
    k_scan3  <<<(NNODES + 255) / 256, 256>>>();
    k_scatter<<<(NEDGES + 255) / 256, 256>>>(src, dst);
    k_node1  <<<(NNODES + 15) / 16, 256>>>(x, Wm1, bm1, Ws1, bs1);
    k_agg1   <<<NNODES / 8, 256>>>(Wm1, Wm2, bm2, Ws2, bs2);
    k_agg2   <<<NNODES / 8, 256>>>(Wm2, Wl3, bl3, out);
}